// round 16
// baseline (speedup 1.0000x reference)
#include <cuda_runtime.h>
#include <cstdint>

#define DD 32          // embed dim
#define GI_W 96        // 3*DD gate width
#define NSYM 64        // distinct path symbol values

typedef uint32_t u32;

// ---------------------------------------------------------------------------
// Precomputed tables (device globals: no dynamic allocation allowed)
// ---------------------------------------------------------------------------
// Slot-major GIT: [tab][sym][slot][m], slot = 2c+pp (c: 0=r,1=z,2=n).
// float4 [slot][m] holds gate cols 32c+16pp+8ntl+2m+e at component 2*ntl+e.
// Biases folded: r/z have +b_ih+b_hh, n has +b_ih.
__device__ float4 g_GIT3[2][NSYM][6][4];
__device__ float g_H2[NSYM * NSYM * DD];   // tf32-rounded GRU state after 2 steps
// W_hh B fragments under k-permutation pi(b,p) = 8b+2p (p<4) / 8b+2(p-4)+1:
// the A fragment of the next step equals the lane's own C fragment.
__device__ float4 g_Bfrag[12][2][32];
__device__ float  g_bhn[DD];               // b_hh[64..95] (n-gate hidden bias)
__device__ float  g_wlr[DD];               // tf32-rounded w_lin

// ---------------------------------------------------------------------------
// TF32 emulation (reference matmuls are TF32 tensor-core GEMMs)
// ---------------------------------------------------------------------------
__device__ __forceinline__ float tf32r(float x) {
    float r;
    asm("cvt.rna.tf32.f32 %0, %1;" : "=f"(r) : "f"(x));
    return r;
}

// MUFU-native activations (abs err ~1e-5, proven negligible vs TF32 floor)
__device__ __forceinline__ float tanh_mufu(float x) {
    float r;
    asm("tanh.approx.f32 %0, %1;" : "=f"(r) : "f"(x));
    return r;
}
__device__ __forceinline__ float sig_mufu(float x) {
    return fmaf(0.5f, tanh_mufu(0.5f * x), 0.5f);
}

// f16x2 pack/unpack (explicit ordering: lo in low half)
__device__ __forceinline__ u32 packh2(float lo, float hi) {
    u32 d;
    asm("{.reg .f16 l,h; cvt.rn.f16.f32 l,%1; cvt.rn.f16.f32 h,%2; mov.b32 %0,{l,h};}"
        : "=r"(d) : "f"(lo), "f"(hi));
    return d;
}
__device__ __forceinline__ void unpackh2(u32 d, float& lo, float& hi) {
    asm("{.reg .f16 l,h; mov.b32 {l,h},%2; cvt.f32.f16 %0,l; cvt.f32.f16 %1,h;}"
        : "=f"(lo), "=f"(hi) : "r"(d));
}

// tf32 MMA: D(16x8) += A(16x8) * B(8x8), fp32 accumulate
__device__ __forceinline__ void mma8(float c[4], const u32 a[4], u32 b0, u32 b1) {
    asm volatile(
        "mma.sync.aligned.m16n8k8.row.col.f32.tf32.tf32.f32 "
        "{%0,%1,%2,%3}, {%4,%5,%6,%7}, {%8,%9}, {%0,%1,%2,%3};"
        : "+f"(c[0]), "+f"(c[1]), "+f"(c[2]), "+f"(c[3])
        : "r"(a[0]), "r"(a[1]), "r"(a[2]), "r"(a[3]), "r"(b0), "r"(b1));
}

// ---------------------------------------------------------------------------
// One MMA GRU step on NT m16-tiles (16*NT paths/warp). State = Ah: tf32 bit
// patterns in A-fragment layout (slot 0=hf0e0, 1=hf1e0, 2=hf0e1, 3=hf1e1).
// r and n carried packed f16x2 (rnpk, in place); z pre-acts packed f16x2.
// ix[tt][hf] = sym*24 + m (GIT3 lane offsets).
// ---------------------------------------------------------------------------
template<int NT>
__device__ __forceinline__ void gru_step(
        u32 (*Ah)[4][4],
        const float4* __restrict__ gt,        // &g_GIT3[tab][0][0][0]
        const int (&ix)[NT][2],
        const float4 (*sB)[2][32],
        const float* __restrict__ sBhn,
        int lane, int m) {
    u32 rnpk[NT][4][2];   // r, then n, packed f16x2 {e0,e1-pair}
    u32 zpk[NT][4][2];

    // --- r gates (slots 0..1, B frags 0..3) ---
    #pragma unroll
    for (int pp = 0; pp < 2; pp++) {
        float4 g[NT][2];
        #pragma unroll
        for (int tt = 0; tt < NT; tt++) {
            g[tt][0] = __ldg(gt + ix[tt][0] + 4 * pp);
            g[tt][1] = __ldg(gt + ix[tt][1] + 4 * pp);
        }
        #pragma unroll
        for (int ntl = 0; ntl < 2; ntl++) {
            int nt = 2 * pp + ntl;
            float4 b0 = sB[nt][0][lane];
            float4 b1 = sB[nt][1][lane];
            #pragma unroll
            for (int tt = 0; tt < NT; tt++) {
                float4 ga = g[tt][0], gb = g[tt][1];
                float c[4];
                c[0] = ntl ? ga.z : ga.x; c[1] = ntl ? ga.w : ga.y;
                c[2] = ntl ? gb.z : gb.x; c[3] = ntl ? gb.w : gb.y;
                mma8(c, Ah[tt][0], __float_as_uint(b0.x), __float_as_uint(b0.y));
                mma8(c, Ah[tt][1], __float_as_uint(b0.z), __float_as_uint(b0.w));
                mma8(c, Ah[tt][2], __float_as_uint(b1.x), __float_as_uint(b1.y));
                mma8(c, Ah[tt][3], __float_as_uint(b1.z), __float_as_uint(b1.w));
                rnpk[tt][nt][0] = packh2(sig_mufu(c[0]), sig_mufu(c[1]));
                rnpk[tt][nt][1] = packh2(sig_mufu(c[2]), sig_mufu(c[3]));
            }
        }
    }

    // --- z gates (slots 2..3, B frags 4..7): raw pre-act packed f16x2 ---
    #pragma unroll
    for (int pp = 0; pp < 2; pp++) {
        float4 g[NT][2];
        #pragma unroll
        for (int tt = 0; tt < NT; tt++) {
            g[tt][0] = __ldg(gt + ix[tt][0] + 8 + 4 * pp);
            g[tt][1] = __ldg(gt + ix[tt][1] + 8 + 4 * pp);
        }
        #pragma unroll
        for (int ntl = 0; ntl < 2; ntl++) {
            int nt = 2 * pp + ntl;
            float4 b0 = sB[4 + nt][0][lane];
            float4 b1 = sB[4 + nt][1][lane];
            #pragma unroll
            for (int tt = 0; tt < NT; tt++) {
                float4 ga = g[tt][0], gb = g[tt][1];
                float c[4];
                c[0] = ntl ? ga.z : ga.x; c[1] = ntl ? ga.w : ga.y;
                c[2] = ntl ? gb.z : gb.x; c[3] = ntl ? gb.w : gb.y;
                mma8(c, Ah[tt][0], __float_as_uint(b0.x), __float_as_uint(b0.y));
                mma8(c, Ah[tt][1], __float_as_uint(b0.z), __float_as_uint(b0.w));
                mma8(c, Ah[tt][2], __float_as_uint(b1.x), __float_as_uint(b1.y));
                mma8(c, Ah[tt][3], __float_as_uint(b1.z), __float_as_uint(b1.w));
                zpk[tt][nt][0] = packh2(c[0], c[1]);
                zpk[tt][nt][1] = packh2(c[2], c[3]);
            }
        }
    }

    // --- n gates (slots 4..5, B frags 8..11): n = tanh(r*gh_n + gi_n) ---
    #pragma unroll
    for (int pp = 0; pp < 2; pp++) {
        float4 g[NT][2];
        #pragma unroll
        for (int tt = 0; tt < NT; tt++) {
            g[tt][0] = __ldg(gt + ix[tt][0] + 16 + 4 * pp);
            g[tt][1] = __ldg(gt + ix[tt][1] + 16 + 4 * pp);
        }
        #pragma unroll
        for (int ntl = 0; ntl < 2; ntl++) {
            int nt = 2 * pp + ntl;
            float2 bb = *(const float2*)&sBhn[8 * nt + 2 * m];
            float4 b0 = sB[8 + nt][0][lane];
            float4 b1 = sB[8 + nt][1][lane];
            #pragma unroll
            for (int tt = 0; tt < NT; tt++) {
                float4 ga = g[tt][0], gb = g[tt][1];
                float gi[4];
                gi[0] = ntl ? ga.z : ga.x; gi[1] = ntl ? ga.w : ga.y;
                gi[2] = ntl ? gb.z : gb.x; gi[3] = ntl ? gb.w : gb.y;
                float ch[4] = {bb.x, bb.y, bb.x, bb.y};
                mma8(ch, Ah[tt][0], __float_as_uint(b0.x), __float_as_uint(b0.y));
                mma8(ch, Ah[tt][1], __float_as_uint(b0.z), __float_as_uint(b0.w));
                mma8(ch, Ah[tt][2], __float_as_uint(b1.x), __float_as_uint(b1.y));
                mma8(ch, Ah[tt][3], __float_as_uint(b1.z), __float_as_uint(b1.w));
                float r0, r1, r2, r3;
                unpackh2(rnpk[tt][nt][0], r0, r1);
                unpackh2(rnpk[tt][nt][1], r2, r3);
                float n0 = tanh_mufu(fmaf(r0, ch[0], gi[0]));
                float n1 = tanh_mufu(fmaf(r1, ch[1], gi[1]));
                float n2 = tanh_mufu(fmaf(r2, ch[2], gi[2]));
                float n3 = tanh_mufu(fmaf(r3, ch[3], gi[3]));
                rnpk[tt][nt][0] = packh2(n0, n1);
                rnpk[tt][nt][1] = packh2(n2, n3);
            }
        }
    }

    // --- update: z = sig(unpack), h = n + z*(h-n), tf32-round into Ah ---
    // C index e -> Ah slot: {0->0, 1->2, 2->1, 3->3}
    #pragma unroll
    for (int tt = 0; tt < NT; tt++) {
        #pragma unroll
        for (int nt = 0; nt < 4; nt++) {
            float za, zb, zc, zd;
            unpackh2(zpk[tt][nt][0], za, zb);
            unpackh2(zpk[tt][nt][1], zc, zd);
            float z0 = sig_mufu(za), z1 = sig_mufu(zb);
            float z2 = sig_mufu(zc), z3 = sig_mufu(zd);
            float n0, n1, n2, n3;
            unpackh2(rnpk[tt][nt][0], n0, n1);
            unpackh2(rnpk[tt][nt][1], n2, n3);
            float h0 = __uint_as_float(Ah[tt][nt][0]);
            float h1 = __uint_as_float(Ah[tt][nt][2]);
            float h2 = __uint_as_float(Ah[tt][nt][1]);
            float h3 = __uint_as_float(Ah[tt][nt][3]);
            Ah[tt][nt][0] = __float_as_uint(tf32r(fmaf(z0, h0 - n0, n0)));
            Ah[tt][nt][2] = __float_as_uint(tf32r(fmaf(z1, h1 - n1, n1)));
            Ah[tt][nt][1] = __float_as_uint(tf32r(fmaf(z2, h2 - n2, n2)));
            Ah[tt][nt][3] = __float_as_uint(tf32r(fmaf(z3, h3 - n3, n3)));
        }
    }
}

// ---------------------------------------------------------------------------
// K_setup: fused zero + GIT3 + Bfrag + bhn + wl. GIT3 uses 4 threads per
// entry (8 MACs each + quad shfl-reduce) to quadruple latency hiding.
// segments: [0,49152) GIT3 | [49152,50176) zero | [50176,50944) Bfrag
//           [50944,50976) bhn | [50976,51008) wl
// ---------------------------------------------------------------------------
__global__ void k_setup(float* out, int out_size,
                        const float* __restrict__ all_emb,
                        const float* __restrict__ edge_emb,
                        const float* __restrict__ w_ih,
                        const float* __restrict__ w_hh,
                        const float* __restrict__ b_ih,
                        const float* __restrict__ b_hh,
                        const float* __restrict__ w_lin) {
    int i = blockIdx.x * blockDim.x + threadIdx.x;
    if (i < 49152) {               // GIT3: 4 threads per entry
        int entry = i >> 2, sub = i & 3;
        int tab = entry / 6144, rem = entry % 6144;
        int sym = rem / GI_W, j = rem % GI_W;
        const float* x = tab ? (edge_emb + sym * DD) : (all_emb + sym * DD);
        const float* w = w_ih + j * DD;
        float a = 0.0f;
        #pragma unroll
        for (int k = 0; k < 8; k++) {
            int kk = 8 * sub + k;
            a = fmaf(tf32r(__ldg(w + kk)), tf32r(__ldg(x + kk)), a);
        }
        a += __shfl_xor_sync(0xffffffffu, a, 1);
        a += __shfl_xor_sync(0xffffffffu, a, 2);
        if (sub == 0) {
            float v = a + __ldg(b_ih + j);
            if (j < 64) v += __ldg(b_hh + j);   // fold b_hh for r/z gates
            // slot-major: col j = 32c + 16pp + 8ntl + 2m + e
            //   -> GIT3[tab][sym][2c+pp][m] component 2*ntl+e
            int c = j >> 5, r5 = j & 31;
            int pp = r5 >> 4, r4 = r5 & 15;
            int ntl = r4 >> 3, r3 = r4 & 7;
            int mm = r3 >> 1, e = r3 & 1;
            float* dst = (float*)&g_GIT3[tab][sym][0][0];
            dst[((2 * c + pp) * 4 + mm) * 4 + 2 * ntl + e] = v;
        }
        return;
    }
    int z = i - 49152;
    if (z < 1024) {
        for (int k = z; k < out_size; k += 1024) out[k] = 0.0f;
        return;
    }
    int j = i - 50176;
    if (j >= 0 && j < 768) {       // W_hh B fragments with pi permutation
        int lane = j & 31;
        int r1 = j >> 5;           // 0..23
        int kp = r1 & 1;
        int nt = r1 >> 1;          // 0..11
        int row = 8 * nt + (lane >> 2);
        int q = lane & 3;
        g_Bfrag[nt][kp][lane] = make_float4(
            tf32r(w_hh[row * DD + 16 * kp + 2 * q]),
            tf32r(w_hh[row * DD + 16 * kp + 2 * q + 1]),
            tf32r(w_hh[row * DD + 16 * kp + 8 + 2 * q]),
            tf32r(w_hh[row * DD + 16 * kp + 8 + 2 * q + 1]));
        return;
    }
    int k = i - 50944;
    if (k >= 0 && k < DD) { g_bhn[k] = b_hh[64 + k]; return; }
    int w = i - 50976;
    if (w >= 0 && w < DD) g_wlr[w] = tf32r(w_lin[w]);
}

// ---------------------------------------------------------------------------
// K_h2: H2 table. h1 computed inline from GIT3 (step 1 from h0=0 is
// elementwise), then one MMA GRU step. NT=1: one warp = 16 keys.
// ---------------------------------------------------------------------------
__global__ void __launch_bounds__(128) k_h2(int dummy) {
    __shared__ float4 sB[12][2][32];
    __shared__ float sBhn[DD];
    int tid = threadIdx.x;
    {
        const float4* src = &g_Bfrag[0][0][0];
        float4* dst = &sB[0][0][0];
        for (int i = tid; i < 768; i += 128) dst[i] = src[i];
        if (tid < DD) sBhn[tid] = g_bhn[tid];
    }
    __syncthreads();

    int lane = tid & 31, m = lane & 3, grp = lane >> 2;
    int kbase = (blockIdx.x * 4 + (tid >> 5)) * 16;

    u32 Ah[1][4][4];
    int ix[1][2];
    #pragma unroll
    for (int hf = 0; hf < 2; hf++) {
        int key = kbase + grp + 8 * hf;
        int e0 = key >> 6;
        ix[0][hf] = (key & 63) * 24 + m;
        const float4* G = &g_GIT3[0][e0][0][m];
        float4 R0 = __ldg(G + 0),  R1 = __ldg(G + 4);
        float4 Z0 = __ldg(G + 8),  Z1 = __ldg(G + 12);
        float4 N0 = __ldg(G + 16), N1 = __ldg(G + 20);
        #pragma unroll
        for (int nt = 0; nt < 4; nt++) {
            int pp = nt >> 1, ntl = nt & 1;
            float4 R = pp ? R1 : R0;
            float4 Z = pp ? Z1 : Z0;
            float4 N = pp ? N1 : N0;
            #pragma unroll
            for (int e = 0; e < 2; e++) {
                float rv = ntl ? (e ? R.w : R.z) : (e ? R.y : R.x);
                float zv = ntl ? (e ? Z.w : Z.z) : (e ? Z.y : Z.x);
                float nv = ntl ? (e ? N.w : N.z) : (e ? N.y : N.x);
                float r = sig_mufu(rv);
                float z = sig_mufu(zv);
                float n = tanh_mufu(fmaf(r, sBhn[8 * nt + 2 * m + e], nv));
                float h1 = (1.0f - z) * n;
                Ah[0][nt][(e ? 2 : 0) + hf] = __float_as_uint(tf32r(h1));
            }
        }
    }

    gru_step<1>(Ah, &g_GIT3[1][0][0][0], ix, sB, sBhn, lane, m);

    int key0 = kbase + grp;
    int key1 = key0 + 8;
    float* D0 = g_H2 + key0 * DD;
    float* D1 = g_H2 + key1 * DD;
    #pragma unroll
    for (int nt = 0; nt < 4; nt++) {
        *(float2*)(D0 + 8 * nt + 2 * m) = make_float2(
            __uint_as_float(Ah[0][nt][0]), __uint_as_float(Ah[0][nt][2]));
        *(float2*)(D1 + 8 * nt + 2 * m) = make_float2(
            __uint_as_float(Ah[0][nt][1]), __uint_as_float(Ah[0][nt][3]));
    }
}

// ---------------------------------------------------------------------------
// K_main: one warp = 32 paths (2 m16 tiles). tf32-valued state in Ah only;
// r/n/z carried packed f16x2 -> register budget fits 5 blocks/SM.
// ---------------------------------------------------------------------------
__global__ void __launch_bounds__(128, 5) k_main(
        const int* __restrict__ path, const int* __restrict__ path_idx,
        const float* __restrict__ b_lin, float* __restrict__ out, int n_paths) {
    __shared__ float4 sB[12][2][32];
    __shared__ float sBhn[DD];
    __shared__ float sWl[DD];

    int tid = threadIdx.x;
    {
        const float4* src = &g_Bfrag[0][0][0];
        float4* dst = &sB[0][0][0];
        for (int i = tid; i < 768; i += 128) dst[i] = src[i];
        if (tid < DD) sBhn[tid] = g_bhn[tid];
        if (tid >= 64 && tid < 64 + DD) sWl[tid - 64] = g_wlr[tid - 64];
    }
    __syncthreads();

    int lane = tid & 31, m = lane & 3, grp = lane >> 2;
    int pbase = (blockIdx.x * 4 + (tid >> 5)) * 32;
    int n1 = n_paths - 1;

    int spk[2][2];                 // [tile][half]: b2 | b3<<8 | b4<<16
    u32 Ah[2][4][4];
    #pragma unroll
    for (int tt = 0; tt < 2; tt++) {
        #pragma unroll
        for (int hf = 0; hf < 2; hf++) {
            int p = min(pbase + 16 * tt + grp + 8 * hf, n1);
            const int* P = path + p * 5;
            int b0 = __ldg(P + 0), b1 = __ldg(P + 1);
            spk[tt][hf] = __ldg(P + 2) | (__ldg(P + 3) << 8) | (__ldg(P + 4) << 16);
            const float* H = g_H2 + (b0 * NSYM + b1) * DD;
            #pragma unroll
            for (int nt = 0; nt < 4; nt++) {
                float2 v = *(const float2*)(H + 8 * nt + 2 * m);
                Ah[tt][nt][0 + hf] = __float_as_uint(v.x);   // e0
                Ah[tt][nt][2 + hf] = __float_as_uint(v.y);   // e1
            }
        }
    }

    #pragma unroll 1
    for (int t = 0; t < 3; t++) {
        int tab = (t == 1) ? 1 : 0;
        int sh = 8 * t;
        int ix[2][2] = {
            {((spk[0][0] >> sh) & 63) * 24 + m, ((spk[0][1] >> sh) & 63) * 24 + m},
            {((spk[1][0] >> sh) & 63) * 24 + m, ((spk[1][1] >> sh) & 63) * 24 + m}};
        gru_step<2>(Ah, &g_GIT3[tab][0][0][0], ix, sB, sBhn, lane, m);
    }

    // Head: s = tf32(h) . tf32(w_lin) + b_lin — Ah already holds tf32(h)
    float bl = __ldg(b_lin);
    #pragma unroll
    for (int tt = 0; tt < 2; tt++) {
        float sc0 = 0.0f, sc1 = 0.0f;
        #pragma unroll
        for (int nt = 0; nt < 4; nt++) {
            float2 wl = *(const float2*)&sWl[8 * nt + 2 * m];
            sc0 = fmaf(__uint_as_float(Ah[tt][nt][0]), wl.x, sc0);
            sc0 = fmaf(__uint_as_float(Ah[tt][nt][2]), wl.y, sc0);
            sc1 = fmaf(__uint_as_float(Ah[tt][nt][1]), wl.x, sc1);
            sc1 = fmaf(__uint_as_float(Ah[tt][nt][3]), wl.y, sc1);
        }
        sc0 += __shfl_xor_sync(0xffffffffu, sc0, 1);
        sc0 += __shfl_xor_sync(0xffffffffu, sc0, 2);
        sc1 += __shfl_xor_sync(0xffffffffu, sc1, 1);
        sc1 += __shfl_xor_sync(0xffffffffu, sc1, 2);
        if (m == 0) {
            int p0 = pbase + 16 * tt + grp;
            int p1 = p0 + 8;
            if (p0 < n_paths) atomicAdd(out + __ldg(path_idx + p0), sc0 + bl);
            if (p1 < n_paths) atomicAdd(out + __ldg(path_idx + p1), sc1 + bl);
        }
    }
}

// ---------------------------------------------------------------------------
extern "C" void kernel_launch(void* const* d_in, const int* in_sizes, int n_in,
                              void* d_out, int out_size) {
    // inputs: 0 users, 1 path, 2 path_idx, 3 all_emb, 4 edge_emb, 5 virtual_emb,
    //         6 w_ih, 7 w_hh, 8 b_ih, 9 b_hh, 10 w_lin, 11 b_lin
    const int*   path     = (const int*)d_in[1];
    const int*   path_idx = (const int*)d_in[2];
    const float* all_emb  = (const float*)d_in[3];
    const float* edge_emb = (const float*)d_in[4];
    const float* w_ih     = (const float*)d_in[6];
    const float* w_hh     = (const float*)d_in[7];
    const float* b_ih     = (const float*)d_in[8];
    const float* b_hh     = (const float*)d_in[9];
    const float* w_lin    = (const float*)d_in[10];
    const float* b_lin    = (const float*)d_in[11];
    float* out = (float*)d_out;
    int n_paths = in_sizes[2];

    k_setup<<<200, 256>>>(out, out_size, all_emb, edge_emb, w_ih, w_hh,
                          b_ih, b_hh, w_lin);
    k_h2<<<64, 128>>>(0);
    int nblocks = (n_paths + 127) / 128;   // 128 paths per block (4 warps x 32)
    k_main<<<nblocks, 128>>>(path, path_idx, b_lin, out, n_paths);
}

// round 17
// speedup vs baseline: 1.6192x; 1.6192x over previous
#include <cuda_runtime.h>
#include <cstdint>

#define DD 32          // embed dim
#define GI_W 96        // 3*DD gate width
#define NSYM 64        // distinct path symbol values

typedef uint32_t u32;

// ---------------------------------------------------------------------------
// Precomputed tables (device globals: no dynamic allocation allowed)
// ---------------------------------------------------------------------------
// Slot-major GIT: [tab][sym][slot][m], slot = 2c+pp (c: 0=r,1=z,2=n).
// float4 [slot][m] holds gate cols 32c+16pp+8ntl+2m+e at component 2*ntl+e.
// Biases folded: r/z have +b_ih+b_hh, n has +b_ih.
__device__ float4 g_GIT3[2][NSYM][6][4];
__device__ float g_H2[NSYM * NSYM * DD];   // tf32-rounded GRU state after 2 steps
// W_hh B fragments under k-permutation pi(b,p) = 8b+2p (p<4) / 8b+2(p-4)+1:
// the A fragment of the next step equals the lane's own C fragment.
__device__ float4 g_Bfrag[12][2][32];
__device__ float  g_bhn[DD];               // b_hh[64..95] (n-gate hidden bias)
__device__ float  g_wlr[DD];               // tf32-rounded w_lin

// ---------------------------------------------------------------------------
// TF32 emulation (reference matmuls are TF32 tensor-core GEMMs)
// ---------------------------------------------------------------------------
__device__ __forceinline__ float tf32r(float x) {
    float r;
    asm("cvt.rna.tf32.f32 %0, %1;" : "=f"(r) : "f"(x));
    return r;
}

// MUFU-native activations (abs err ~1e-5, proven negligible vs TF32 floor)
__device__ __forceinline__ float tanh_mufu(float x) {
    float r;
    asm("tanh.approx.f32 %0, %1;" : "=f"(r) : "f"(x));
    return r;
}
__device__ __forceinline__ float sig_mufu(float x) {
    return fmaf(0.5f, tanh_mufu(0.5f * x), 0.5f);
}

// f16x2 pack/unpack (explicit ordering: lo in low half)
__device__ __forceinline__ u32 packh2(float lo, float hi) {
    u32 d;
    asm("{.reg .f16 l,h; cvt.rn.f16.f32 l,%1; cvt.rn.f16.f32 h,%2; mov.b32 %0,{l,h};}"
        : "=r"(d) : "f"(lo), "f"(hi));
    return d;
}
__device__ __forceinline__ void unpackh2(u32 d, float& lo, float& hi) {
    asm("{.reg .f16 l,h; mov.b32 {l,h},%2; cvt.f32.f16 %0,l; cvt.f32.f16 %1,h;}"
        : "=f"(lo), "=f"(hi) : "r"(d));
}

// tf32 MMA: D(16x8) += A(16x8) * B(8x8), fp32 accumulate
__device__ __forceinline__ void mma8(float c[4], const u32 a[4], u32 b0, u32 b1) {
    asm volatile(
        "mma.sync.aligned.m16n8k8.row.col.f32.tf32.tf32.f32 "
        "{%0,%1,%2,%3}, {%4,%5,%6,%7}, {%8,%9}, {%0,%1,%2,%3};"
        : "+f"(c[0]), "+f"(c[1]), "+f"(c[2]), "+f"(c[3])
        : "r"(a[0]), "r"(a[1]), "r"(a[2]), "r"(a[3]), "r"(b0), "r"(b1));
}

// ---------------------------------------------------------------------------
// One MMA GRU step on NT m16-tiles (16*NT paths/warp). State = Ah: tf32 bit
// patterns in A-fragment layout (slot 0=hf0e0, 1=hf1e0, 2=hf0e1, 3=hf1e1).
// z gates computed before n, stored as raw pre-activations packed f16x2.
// ix[tt][hf] = sym*24 + m (GIT3 lane offsets).
// ---------------------------------------------------------------------------
template<int NT>
__device__ __forceinline__ void gru_step(
        u32 (*Ah)[4][4],
        const float4* __restrict__ gt,        // &g_GIT3[tab][0][0][0]
        const int (&ix)[NT][2],
        const float4 (*sB)[2][32],
        const float* __restrict__ sBhn,
        int lane, int m) {
    float rn[NT][4][4];
    u32   zpk[NT][4][2];

    // --- r gates (slots 0..1, B frags 0..3) ---
    #pragma unroll
    for (int pp = 0; pp < 2; pp++) {
        float4 g[NT][2];
        #pragma unroll
        for (int tt = 0; tt < NT; tt++) {
            g[tt][0] = __ldg(gt + ix[tt][0] + 4 * pp);
            g[tt][1] = __ldg(gt + ix[tt][1] + 4 * pp);
        }
        #pragma unroll
        for (int ntl = 0; ntl < 2; ntl++) {
            int nt = 2 * pp + ntl;
            float4 b0 = sB[nt][0][lane];
            float4 b1 = sB[nt][1][lane];
            #pragma unroll
            for (int tt = 0; tt < NT; tt++) {
                float4 ga = g[tt][0], gb = g[tt][1];
                float c[4];
                c[0] = ntl ? ga.z : ga.x; c[1] = ntl ? ga.w : ga.y;
                c[2] = ntl ? gb.z : gb.x; c[3] = ntl ? gb.w : gb.y;
                mma8(c, Ah[tt][0], __float_as_uint(b0.x), __float_as_uint(b0.y));
                mma8(c, Ah[tt][1], __float_as_uint(b0.z), __float_as_uint(b0.w));
                mma8(c, Ah[tt][2], __float_as_uint(b1.x), __float_as_uint(b1.y));
                mma8(c, Ah[tt][3], __float_as_uint(b1.z), __float_as_uint(b1.w));
                rn[tt][nt][0] = sig_mufu(c[0]);
                rn[tt][nt][1] = sig_mufu(c[1]);
                rn[tt][nt][2] = sig_mufu(c[2]);
                rn[tt][nt][3] = sig_mufu(c[3]);
            }
        }
    }

    // --- z gates (slots 2..3, B frags 4..7): raw pre-act packed f16x2 ---
    #pragma unroll
    for (int pp = 0; pp < 2; pp++) {
        float4 g[NT][2];
        #pragma unroll
        for (int tt = 0; tt < NT; tt++) {
            g[tt][0] = __ldg(gt + ix[tt][0] + 8 + 4 * pp);
            g[tt][1] = __ldg(gt + ix[tt][1] + 8 + 4 * pp);
        }
        #pragma unroll
        for (int ntl = 0; ntl < 2; ntl++) {
            int nt = 2 * pp + ntl;
            float4 b0 = sB[4 + nt][0][lane];
            float4 b1 = sB[4 + nt][1][lane];
            #pragma unroll
            for (int tt = 0; tt < NT; tt++) {
                float4 ga = g[tt][0], gb = g[tt][1];
                float c[4];
                c[0] = ntl ? ga.z : ga.x; c[1] = ntl ? ga.w : ga.y;
                c[2] = ntl ? gb.z : gb.x; c[3] = ntl ? gb.w : gb.y;
                mma8(c, Ah[tt][0], __float_as_uint(b0.x), __float_as_uint(b0.y));
                mma8(c, Ah[tt][1], __float_as_uint(b0.z), __float_as_uint(b0.w));
                mma8(c, Ah[tt][2], __float_as_uint(b1.x), __float_as_uint(b1.y));
                mma8(c, Ah[tt][3], __float_as_uint(b1.z), __float_as_uint(b1.w));
                zpk[tt][nt][0] = packh2(c[0], c[1]);
                zpk[tt][nt][1] = packh2(c[2], c[3]);
            }
        }
    }

    // --- n gates (slots 4..5, B frags 8..11): n = tanh(r*gh_n + gi_n) ---
    #pragma unroll
    for (int pp = 0; pp < 2; pp++) {
        float4 g[NT][2];
        #pragma unroll
        for (int tt = 0; tt < NT; tt++) {
            g[tt][0] = __ldg(gt + ix[tt][0] + 16 + 4 * pp);
            g[tt][1] = __ldg(gt + ix[tt][1] + 16 + 4 * pp);
        }
        #pragma unroll
        for (int ntl = 0; ntl < 2; ntl++) {
            int nt = 2 * pp + ntl;
            float2 bb = *(const float2*)&sBhn[8 * nt + 2 * m];
            float4 b0 = sB[8 + nt][0][lane];
            float4 b1 = sB[8 + nt][1][lane];
            #pragma unroll
            for (int tt = 0; tt < NT; tt++) {
                float4 ga = g[tt][0], gb = g[tt][1];
                float gi[4];
                gi[0] = ntl ? ga.z : ga.x; gi[1] = ntl ? ga.w : ga.y;
                gi[2] = ntl ? gb.z : gb.x; gi[3] = ntl ? gb.w : gb.y;
                float ch[4] = {bb.x, bb.y, bb.x, bb.y};
                mma8(ch, Ah[tt][0], __float_as_uint(b0.x), __float_as_uint(b0.y));
                mma8(ch, Ah[tt][1], __float_as_uint(b0.z), __float_as_uint(b0.w));
                mma8(ch, Ah[tt][2], __float_as_uint(b1.x), __float_as_uint(b1.y));
                mma8(ch, Ah[tt][3], __float_as_uint(b1.z), __float_as_uint(b1.w));
                rn[tt][nt][0] = tanh_mufu(fmaf(rn[tt][nt][0], ch[0], gi[0]));
                rn[tt][nt][1] = tanh_mufu(fmaf(rn[tt][nt][1], ch[1], gi[1]));
                rn[tt][nt][2] = tanh_mufu(fmaf(rn[tt][nt][2], ch[2], gi[2]));
                rn[tt][nt][3] = tanh_mufu(fmaf(rn[tt][nt][3], ch[3], gi[3]));
            }
        }
    }

    // --- update: z = sig(unpack), h = n + z*(h-n), tf32-round into Ah ---
    // C index e -> Ah slot: {0->0, 1->2, 2->1, 3->3}
    #pragma unroll
    for (int tt = 0; tt < NT; tt++) {
        #pragma unroll
        for (int nt = 0; nt < 4; nt++) {
            float za, zb, zc, zd;
            unpackh2(zpk[tt][nt][0], za, zb);
            unpackh2(zpk[tt][nt][1], zc, zd);
            float z0 = sig_mufu(za), z1 = sig_mufu(zb);
            float z2 = sig_mufu(zc), z3 = sig_mufu(zd);
            float h0 = __uint_as_float(Ah[tt][nt][0]);
            float h1 = __uint_as_float(Ah[tt][nt][2]);
            float h2 = __uint_as_float(Ah[tt][nt][1]);
            float h3 = __uint_as_float(Ah[tt][nt][3]);
            float n0 = rn[tt][nt][0], n1 = rn[tt][nt][1];
            float n2 = rn[tt][nt][2], n3 = rn[tt][nt][3];
            Ah[tt][nt][0] = __float_as_uint(tf32r(fmaf(z0, h0 - n0, n0)));
            Ah[tt][nt][2] = __float_as_uint(tf32r(fmaf(z1, h1 - n1, n1)));
            Ah[tt][nt][1] = __float_as_uint(tf32r(fmaf(z2, h2 - n2, n2)));
            Ah[tt][nt][3] = __float_as_uint(tf32r(fmaf(z3, h3 - n3, n3)));
        }
    }
}

// ---------------------------------------------------------------------------
// K_setup: fused zero + GIT3 + Bfrag + bhn + wl. GIT3 uses 4 threads per
// entry (8 MACs each + quad shfl-reduce) to quadruple latency hiding.
// segments: [0,49152) GIT3 | [49152,50176) zero | [50176,50944) Bfrag
//           [50944,50976) bhn | [50976,51008) wl
// ---------------------------------------------------------------------------
__global__ void k_setup(float* out, int out_size,
                        const float* __restrict__ all_emb,
                        const float* __restrict__ edge_emb,
                        const float* __restrict__ w_ih,
                        const float* __restrict__ w_hh,
                        const float* __restrict__ b_ih,
                        const float* __restrict__ b_hh,
                        const float* __restrict__ w_lin) {
    int i = blockIdx.x * blockDim.x + threadIdx.x;
    if (i < 49152) {               // GIT3: 4 threads per entry
        int entry = i >> 2, sub = i & 3;
        int tab = entry / 6144, rem = entry % 6144;
        int sym = rem / GI_W, j = rem % GI_W;
        const float* x = tab ? (edge_emb + sym * DD) : (all_emb + sym * DD);
        const float* w = w_ih + j * DD;
        float a = 0.0f;
        #pragma unroll
        for (int k = 0; k < 8; k++) {
            int kk = 8 * sub + k;
            a = fmaf(tf32r(__ldg(w + kk)), tf32r(__ldg(x + kk)), a);
        }
        a += __shfl_xor_sync(0xffffffffu, a, 1);
        a += __shfl_xor_sync(0xffffffffu, a, 2);
        if (sub == 0) {
            float v = a + __ldg(b_ih + j);
            if (j < 64) v += __ldg(b_hh + j);   // fold b_hh for r/z gates
            // slot-major: col j = 32c + 16pp + 8ntl + 2m + e
            //   -> GIT3[tab][sym][2c+pp][m] component 2*ntl+e
            int c = j >> 5, r5 = j & 31;
            int pp = r5 >> 4, r4 = r5 & 15;
            int ntl = r4 >> 3, r3 = r4 & 7;
            int mm = r3 >> 1, e = r3 & 1;
            float* dst = (float*)&g_GIT3[tab][sym][0][0];
            dst[((2 * c + pp) * 4 + mm) * 4 + 2 * ntl + e] = v;
        }
        return;
    }
    int z = i - 49152;
    if (z < 1024) {
        for (int k = z; k < out_size; k += 1024) out[k] = 0.0f;
        return;
    }
    int j = i - 50176;
    if (j >= 0 && j < 768) {       // W_hh B fragments with pi permutation
        int lane = j & 31;
        int r1 = j >> 5;           // 0..23
        int kp = r1 & 1;
        int nt = r1 >> 1;          // 0..11
        int row = 8 * nt + (lane >> 2);
        int q = lane & 3;
        g_Bfrag[nt][kp][lane] = make_float4(
            tf32r(w_hh[row * DD + 16 * kp + 2 * q]),
            tf32r(w_hh[row * DD + 16 * kp + 2 * q + 1]),
            tf32r(w_hh[row * DD + 16 * kp + 8 + 2 * q]),
            tf32r(w_hh[row * DD + 16 * kp + 8 + 2 * q + 1]));
        return;
    }
    int k = i - 50944;
    if (k >= 0 && k < DD) { g_bhn[k] = b_hh[64 + k]; return; }
    int w = i - 50976;
    if (w >= 0 && w < DD) g_wlr[w] = tf32r(w_lin[w]);
}

// ---------------------------------------------------------------------------
// K_h2: H2 table. h1 computed inline from GIT3 (step 1 from h0=0 is
// elementwise), then one MMA GRU step. NT=1: one warp = 16 keys.
// ---------------------------------------------------------------------------
__global__ void __launch_bounds__(128) k_h2(int dummy) {
    __shared__ float4 sB[12][2][32];
    __shared__ float sBhn[DD];
    int tid = threadIdx.x;
    {
        const float4* src = &g_Bfrag[0][0][0];
        float4* dst = &sB[0][0][0];
        for (int i = tid; i < 768; i += 128) dst[i] = src[i];
        if (tid < DD) sBhn[tid] = g_bhn[tid];
    }
    __syncthreads();

    int lane = tid & 31, m = lane & 3, grp = lane >> 2;
    int kbase = (blockIdx.x * 4 + (tid >> 5)) * 16;

    u32 Ah[1][4][4];
    int ix[1][2];
    #pragma unroll
    for (int hf = 0; hf < 2; hf++) {
        int key = kbase + grp + 8 * hf;
        int e0 = key >> 6;
        ix[0][hf] = (key & 63) * 24 + m;
        const float4* G = &g_GIT3[0][e0][0][m];
        float4 R0 = __ldg(G + 0),  R1 = __ldg(G + 4);
        float4 Z0 = __ldg(G + 8),  Z1 = __ldg(G + 12);
        float4 N0 = __ldg(G + 16), N1 = __ldg(G + 20);
        #pragma unroll
        for (int nt = 0; nt < 4; nt++) {
            int pp = nt >> 1, ntl = nt & 1;
            float4 R = pp ? R1 : R0;
            float4 Z = pp ? Z1 : Z0;
            float4 N = pp ? N1 : N0;
            #pragma unroll
            for (int e = 0; e < 2; e++) {
                float rv = ntl ? (e ? R.w : R.z) : (e ? R.y : R.x);
                float zv = ntl ? (e ? Z.w : Z.z) : (e ? Z.y : Z.x);
                float nv = ntl ? (e ? N.w : N.z) : (e ? N.y : N.x);
                float r = sig_mufu(rv);
                float z = sig_mufu(zv);
                float n = tanh_mufu(fmaf(r, sBhn[8 * nt + 2 * m + e], nv));
                float h1 = (1.0f - z) * n;
                Ah[0][nt][(e ? 2 : 0) + hf] = __float_as_uint(tf32r(h1));
            }
        }
    }

    gru_step<1>(Ah, &g_GIT3[1][0][0][0], ix, sB, sBhn, lane, m);

    int key0 = kbase + grp;
    int key1 = key0 + 8;
    float* D0 = g_H2 + key0 * DD;
    float* D1 = g_H2 + key1 * DD;
    #pragma unroll
    for (int nt = 0; nt < 4; nt++) {
        *(float2*)(D0 + 8 * nt + 2 * m) = make_float2(
            __uint_as_float(Ah[0][nt][0]), __uint_as_float(Ah[0][nt][2]));
        *(float2*)(D1 + 8 * nt + 2 * m) = make_float2(
            __uint_as_float(Ah[0][nt][1]), __uint_as_float(Ah[0][nt][3]));
    }
}

// ---------------------------------------------------------------------------
// K_main: 256-thread blocks (8 warps), one warp = 32 paths (2 m16 tiles).
// Same 16 warps/SM occupancy as (128,4) but half the blocks -> half the
// per-block smem-fill + sync + launch overhead. tf32 state in Ah only.
// ---------------------------------------------------------------------------
__global__ void __launch_bounds__(256, 2) k_main(
        const int* __restrict__ path, const int* __restrict__ path_idx,
        const float* __restrict__ b_lin, float* __restrict__ out, int n_paths) {
    __shared__ float4 sB[12][2][32];
    __shared__ float sBhn[DD];
    __shared__ float sWl[DD];

    int tid = threadIdx.x;
    {
        const float4* src = &g_Bfrag[0][0][0];
        float4* dst = &sB[0][0][0];
        for (int i = tid; i < 768; i += 256) dst[i] = src[i];
        if (tid < DD) sBhn[tid] = g_bhn[tid];
        if (tid >= 64 && tid < 64 + DD) sWl[tid - 64] = g_wlr[tid - 64];
    }
    __syncthreads();

    int lane = tid & 31, m = lane & 3, grp = lane >> 2;
    int pbase = (blockIdx.x * 8 + (tid >> 5)) * 32;
    int n1 = n_paths - 1;

    int spk[2][2];                 // [tile][half]: b2 | b3<<8 | b4<<16
    u32 Ah[2][4][4];
    #pragma unroll
    for (int tt = 0; tt < 2; tt++) {
        #pragma unroll
        for (int hf = 0; hf < 2; hf++) {
            int p = min(pbase + 16 * tt + grp + 8 * hf, n1);
            const int* P = path + p * 5;
            int b0 = __ldg(P + 0), b1 = __ldg(P + 1);
            spk[tt][hf] = __ldg(P + 2) | (__ldg(P + 3) << 8) | (__ldg(P + 4) << 16);
            const float* H = g_H2 + (b0 * NSYM + b1) * DD;
            #pragma unroll
            for (int nt = 0; nt < 4; nt++) {
                float2 v = *(const float2*)(H + 8 * nt + 2 * m);
                Ah[tt][nt][0 + hf] = __float_as_uint(v.x);   // e0
                Ah[tt][nt][2 + hf] = __float_as_uint(v.y);   // e1
            }
        }
    }

    #pragma unroll 1
    for (int t = 0; t < 3; t++) {
        int tab = (t == 1) ? 1 : 0;
        int sh = 8 * t;
        int ix[2][2] = {
            {((spk[0][0] >> sh) & 63) * 24 + m, ((spk[0][1] >> sh) & 63) * 24 + m},
            {((spk[1][0] >> sh) & 63) * 24 + m, ((spk[1][1] >> sh) & 63) * 24 + m}};
        gru_step<2>(Ah, &g_GIT3[tab][0][0][0], ix, sB, sBhn, lane, m);
    }

    // Head: s = tf32(h) . tf32(w_lin) + b_lin — Ah already holds tf32(h)
    float bl = __ldg(b_lin);
    #pragma unroll
    for (int tt = 0; tt < 2; tt++) {
        float sc0 = 0.0f, sc1 = 0.0f;
        #pragma unroll
        for (int nt = 0; nt < 4; nt++) {
            float2 wl = *(const float2*)&sWl[8 * nt + 2 * m];
            sc0 = fmaf(__uint_as_float(Ah[tt][nt][0]), wl.x, sc0);
            sc0 = fmaf(__uint_as_float(Ah[tt][nt][2]), wl.y, sc0);
            sc1 = fmaf(__uint_as_float(Ah[tt][nt][1]), wl.x, sc1);
            sc1 = fmaf(__uint_as_float(Ah[tt][nt][3]), wl.y, sc1);
        }
        sc0 += __shfl_xor_sync(0xffffffffu, sc0, 1);
        sc0 += __shfl_xor_sync(0xffffffffu, sc0, 2);
        sc1 += __shfl_xor_sync(0xffffffffu, sc1, 1);
        sc1 += __shfl_xor_sync(0xffffffffu, sc1, 2);
        if (m == 0) {
            int p0 = pbase + 16 * tt + grp;
            int p1 = p0 + 8;
            if (p0 < n_paths) atomicAdd(out + __ldg(path_idx + p0), sc0 + bl);
            if (p1 < n_paths) atomicAdd(out + __ldg(path_idx + p1), sc1 + bl);
        }
    }
}

// ---------------------------------------------------------------------------
extern "C" void kernel_launch(void* const* d_in, const int* in_sizes, int n_in,
                              void* d_out, int out_size) {
    // inputs: 0 users, 1 path, 2 path_idx, 3 all_emb, 4 edge_emb, 5 virtual_emb,
    //         6 w_ih, 7 w_hh, 8 b_ih, 9 b_hh, 10 w_lin, 11 b_lin
    const int*   path     = (const int*)d_in[1];
    const int*   path_idx = (const int*)d_in[2];
    const float* all_emb  = (const float*)d_in[3];
    const float* edge_emb = (const float*)d_in[4];
    const float* w_ih     = (const float*)d_in[6];
    const float* w_hh     = (const float*)d_in[7];
    const float* b_ih     = (const float*)d_in[8];
    const float* b_hh     = (const float*)d_in[9];
    const float* w_lin    = (const float*)d_in[10];
    const float* b_lin    = (const float*)d_in[11];
    float* out = (float*)d_out;
    int n_paths = in_sizes[2];

    k_setup<<<200, 256>>>(out, out_size, all_emb, edge_emb, w_ih, w_hh,
                          b_ih, b_hh, w_lin);
    k_h2<<<64, 128>>>(0);
    int nblocks = (n_paths + 255) / 256;   // 256 paths per block (8 warps x 32)
    k_main<<<nblocks, 256>>>(path, path_idx, b_lin, out, n_paths);
}